// round 15
// baseline (speedup 1.0000x reference)
#include <cuda_runtime.h>
#include <cuda_bf16.h>
#include <cstdint>
#include <math.h>

#define Bv 2
#define Sv 2048
#define Dv 1024
#define Hv 16
#define DHv 64
#define Mv (Bv*Sv)        // 4096
#define PADK 36
#define PADQ 68

// Scratch (module-static device globals; no runtime allocation)
__device__ float g_q[(size_t)Bv*Hv*Sv*DHv];   // [b][h][s][dh]
__device__ float g_k[(size_t)Bv*Hv*Sv*DHv];   // [b][h][s][dh]
__device__ float g_vt[(size_t)Bv*Hv*DHv*Sv];  // [b][h][dh][s]  (V transposed)
__device__ float g_o[(size_t)Bv*Sv*Dv];       // [b][s][h*DH+dh]
__device__ float g_wt[(size_t)3*Hv*DHv*Dv];   // W^T per matrix/head: [mtx][h][n][k]
__device__ float g_wot[(size_t)Dv*Dv];        // Wo^T: [n][k]

// ---------------------------------------------------------------------------
// tf32 helpers (mma.sync path — tcgen05 unavailable on this build target)
// ---------------------------------------------------------------------------
__device__ __forceinline__ uint32_t f2tf(float x) {
    uint32_t r;
    asm("cvt.rna.tf32.f32 %0, %1;" : "=r"(r) : "f"(x));
    return r;
}

__device__ __forceinline__ void mma_tf32(float* c, const uint32_t* a, const uint32_t* b) {
    asm volatile(
        "mma.sync.aligned.m16n8k8.row.col.f32.tf32.tf32.f32 "
        "{%0,%1,%2,%3}, {%4,%5,%6,%7}, {%8,%9}, {%0,%1,%2,%3};"
        : "+f"(c[0]), "+f"(c[1]), "+f"(c[2]), "+f"(c[3])
        : "r"(a[0]), "r"(a[1]), "r"(a[2]), "r"(a[3]), "r"(b[0]), "r"(b[1]));
}

// ---------------------------------------------------------------------------
// Weight transpose: dst[b][c][r] = src[b][r][c].
// ---------------------------------------------------------------------------
__global__ __launch_bounds__(256) void transpose_kernel(
    const float* __restrict__ src, int R, int C, int which)
{
    __shared__ float t[32][33];
    float* dstbase = (which < 3) ? (g_wt + (size_t)which * Hv * DHv * Dv) : g_wot;

    const int b  = blockIdx.z;
    const float* s = src + (size_t)b * R * C;
    float* d       = dstbase + (size_t)b * R * C;
    const int r0 = blockIdx.x * 32, c0 = blockIdx.y * 32;
    const int tx = threadIdx.x, ty = threadIdx.y;

    #pragma unroll
    for (int i = 0; i < 4; i++)
        t[ty + 8*i][tx] = s[(size_t)(r0 + ty + 8*i) * C + c0 + tx];
    __syncthreads();
    #pragma unroll
    for (int i = 0; i < 4; i++)
        d[(size_t)(c0 + ty + 8*i) * R + r0 + tx] = t[tx][ty + 8*i];
}

// ---------------------------------------------------------------------------
// mma.sync tf32 GEMM core: acc[128x64] += A[128xDv] @ B[64xDv]^T.
// 256 threads = 8 warps in 4(M) x 2(N); warp tile 32x32 = 2x4 m16n8k8 frags.
// ---------------------------------------------------------------------------
__device__ __forceinline__ void gemm_mma_128x64(
    const float* __restrict__ Arows, const float* __restrict__ Brows,
    float acc[2][4][4], float* As /*[128*PADK]*/, float* Bs /*[64*PADK]*/)
{
    const int tid  = threadIdx.x;
    const int wid  = tid >> 5;
    const int lane = tid & 31;
    const int g    = lane >> 2;
    const int t    = lane & 3;
    const int wm   = (wid & 3) * 32;
    const int wn   = (wid >> 2) * 32;

    for (int kc = 0; kc < Dv; kc += 32) {
        #pragma unroll
        for (int l = 0; l < 4; l++) {
            int fid = tid + l * 256;
            int m   = fid >> 3;
            int kq  = fid & 7;
            float4 v = *(const float4*)&Arows[(size_t)m * Dv + kc + kq * 4];
            uint4 u;
            u.x = f2tf(v.x); u.y = f2tf(v.y); u.z = f2tf(v.z); u.w = f2tf(v.w);
            *(uint4*)&As[m * PADK + kq * 4] = u;
        }
        #pragma unroll
        for (int l = 0; l < 2; l++) {
            int fid = tid + l * 256;
            int n   = fid >> 3;
            int kq  = fid & 7;
            float4 v = *(const float4*)&Brows[(size_t)n * Dv + kc + kq * 4];
            uint4 u;
            u.x = f2tf(v.x); u.y = f2tf(v.y); u.z = f2tf(v.z); u.w = f2tf(v.w);
            *(uint4*)&Bs[n * PADK + kq * 4] = u;
        }
        __syncthreads();

        #pragma unroll
        for (int ks = 0; ks < 32; ks += 8) {
            uint32_t a[2][4], b[4][2];
            #pragma unroll
            for (int mi = 0; mi < 2; mi++) {
                int r0 = wm + mi * 16 + g;
                a[mi][0] = __float_as_uint(As[r0 * PADK + ks + t]);
                a[mi][1] = __float_as_uint(As[(r0 + 8) * PADK + ks + t]);
                a[mi][2] = __float_as_uint(As[r0 * PADK + ks + t + 4]);
                a[mi][3] = __float_as_uint(As[(r0 + 8) * PADK + ks + t + 4]);
            }
            #pragma unroll
            for (int ni = 0; ni < 4; ni++) {
                int nr = wn + ni * 8 + g;
                b[ni][0] = __float_as_uint(Bs[nr * PADK + ks + t]);
                b[ni][1] = __float_as_uint(Bs[nr * PADK + ks + t + 4]);
            }
            #pragma unroll
            for (int mi = 0; mi < 2; mi++)
                #pragma unroll
                for (int ni = 0; ni < 4; ni++)
                    mma_tf32(acc[mi][ni], a[mi], b[ni]);
        }
        __syncthreads();
    }
}

// ---------------------------------------------------------------------------
// Kernel 1: QKV projection via mma.sync tf32.  grid(Mv/128, H, 3), block 256.
// V (mtx==2) is written TRANSPOSED to g_vt[b][h][dh][s] for the PV mma.
// ---------------------------------------------------------------------------
__global__ __launch_bounds__(256) void qkv_mma_kernel(
    const float* __restrict__ x,
    const float* __restrict__ bq,
    const float* __restrict__ bk,
    const float* __restrict__ bv)
{
    __shared__ float As[128 * PADK];
    __shared__ float Bs[64 * PADK];

    const int h   = blockIdx.y;
    const int mtx = blockIdx.z;
    const int r0  = blockIdx.x * 128;

    const float* Brows = g_wt + ((size_t)(mtx * Hv + h) * DHv) * Dv;
    const float* bias  = ((mtx == 0) ? bq : (mtx == 1) ? bk : bv) + h * DHv;

    float acc[2][4][4] = {};
    gemm_mma_128x64(x + (size_t)r0 * Dv, Brows, acc, As, Bs);

    const int lane = threadIdx.x & 31;
    const int wid  = threadIdx.x >> 5;
    const int g    = lane >> 2;
    const int t    = lane & 3;
    const int wm   = (wid & 3) * 32;
    const int wn   = (wid >> 2) * 32;

    if (mtx == 2) {
        // transposed store: g_vt[(b*Hv+h)*DHv + col][s]
        #pragma unroll
        for (int mi = 0; mi < 2; mi++) {
            #pragma unroll
            for (int ni = 0; ni < 4; ni++) {
                int col = wn + ni * 8 + 2 * t;
                #pragma unroll
                for (int half = 0; half < 2; half++) {
                    int m = r0 + wm + mi * 16 + g + half * 8;
                    int b = m >> 11;
                    int s = m & (Sv - 1);
                    float* base = g_vt + ((size_t)(b * Hv + h) * DHv) * Sv;
                    base[(size_t)(col + 0) * Sv + s] = acc[mi][ni][2*half + 0] + bias[col + 0];
                    base[(size_t)(col + 1) * Sv + s] = acc[mi][ni][2*half + 1] + bias[col + 1];
                }
            }
        }
    } else {
        float* out = (mtx == 0) ? g_q : g_k;
        #pragma unroll
        for (int mi = 0; mi < 2; mi++) {
            #pragma unroll
            for (int ni = 0; ni < 4; ni++) {
                int col = wn + ni * 8 + 2 * t;
                #pragma unroll
                for (int half = 0; half < 2; half++) {
                    int m = r0 + wm + mi * 16 + g + half * 8;
                    int b = m >> 11;
                    int s = m & (Sv - 1);
                    float* dst = out + ((size_t)(b * Hv + h) * Sv + s) * DHv + col;
                    float2 w;
                    w.x = acc[mi][ni][2*half + 0] + bias[col + 0];
                    w.y = acc[mi][ni][2*half + 1] + bias[col + 1];
                    *(float2*)dst = w;
                }
            }
        }
    }
}

// ---------------------------------------------------------------------------
// Kernel 3: output projection via mma.sync tf32.  grid(Mv/128, Dv/64), block 256.
// ---------------------------------------------------------------------------
__global__ __launch_bounds__(256) void proj_mma_kernel(
    const float* __restrict__ bo, float* __restrict__ out)
{
    __shared__ float As[128 * PADK];
    __shared__ float Bs[64 * PADK];

    const int r0 = blockIdx.x * 128;
    const int n0 = blockIdx.y * 64;

    float acc[2][4][4] = {};
    gemm_mma_128x64(g_o + (size_t)r0 * Dv, g_wot + (size_t)n0 * Dv, acc, As, Bs);

    const int lane = threadIdx.x & 31;
    const int wid  = threadIdx.x >> 5;
    const int g    = lane >> 2;
    const int t    = lane & 3;
    const int wm   = (wid & 3) * 32;
    const int wn   = (wid >> 2) * 32;

    #pragma unroll
    for (int mi = 0; mi < 2; mi++) {
        #pragma unroll
        for (int ni = 0; ni < 4; ni++) {
            int col = n0 + wn + ni * 8 + 2 * t;
            #pragma unroll
            for (int half = 0; half < 2; half++) {
                int m = r0 + wm + mi * 16 + g + half * 8;
                float* dst = out + (size_t)m * Dv + col;
                float2 w;
                w.x = acc[mi][ni][2*half + 0] + bo[col + 0];
                w.y = acc[mi][ni][2*half + 1] + bo[col + 1];
                *(float2*)dst = w;
            }
        }
    }
}

// ---------------------------------------------------------------------------
// Kernel 2: flash attention, 128-row Q tiles.  grid(B*H, S/128), block 384.
// Warps 0-7: compute — warp w owns score/output rows w*16..w*16+15
// end-to-end (S mma -> register softmax -> PV mma; corr/l_run in registers).
// Warps 8-11: loaders — next K tile (g_k, tf32) and V tile (g_vt [dh][s],
// tf32) into the alternate smem buffer during compute.
// One __syncthreads per KV tile.  KV L2 traffic halved vs 64-row tiles.
// Smem (floats): Qs@0[128*68=8704] | Ks0@8704 Ks1@13056 (4352 each) |
//                Vt0@17408 Vt1@21760 | Ps@26112[8704]
//                total 34816 f = 139264 B (1 CTA/SM)
// ---------------------------------------------------------------------------
__global__ __launch_bounds__(384) void attn_kernel()
{
    extern __shared__ float sm[];
    float* Qs = sm;
    float* Ps = sm + 26112;

    const int bh  = blockIdx.x;                 // b*H + h
    const int s0  = blockIdx.y * 128;
    const int tid = threadIdx.x;
    const int wid = tid >> 5;
    const int lane = tid & 31;
    const int g   = lane >> 2;
    const int t   = lane & 3;
    const int wm  = wid * 16;                   // compute warps 0-7

    const float* qbase  = g_q  + (size_t)bh * Sv * DHv;
    const float* kbase  = g_k  + (size_t)bh * Sv * DHv;
    const float* vtbase = g_vt + (size_t)bh * DHv * Sv;

    // All threads: Q tile (128 rows) -> tf32, pre-scaled by 1/8 (exact)
    #pragma unroll
    for (int l = 0; l < 6; l++) {
        int fid = tid + l * 384;                // 0..2303, need 0..2047
        if (fid < 128 * 16) {
            int row = fid >> 4, c = fid & 15;
            float4 v = *(const float4*)&qbase[(size_t)(s0 + row) * DHv + c * 4];
            uint4 u;
            u.x = f2tf(v.x * 0.125f); u.y = f2tf(v.y * 0.125f);
            u.z = f2tf(v.z * 0.125f); u.w = f2tf(v.w * 0.125f);
            *(uint4*)&Qs[row * PADQ + c * 4] = u;
        }
    }

    // Loaders fill buffer 0 with tile 0
    if (wid >= 8) {
        const int ltid = tid - 256;             // 0..127
        float* Kd = sm + 8704;
        float* Vd = sm + 17408;
        #pragma unroll
        for (int l = 0; l < 8; l++) {
            int fid = ltid + l * 128;
            int row = fid >> 4, c = fid & 15;
            float4 kv = *(const float4*)&kbase[(size_t)row * DHv + c * 4];
            uint4 uk;
            uk.x = f2tf(kv.x); uk.y = f2tf(kv.y); uk.z = f2tf(kv.z); uk.w = f2tf(kv.w);
            *(uint4*)&Kd[row * PADQ + c * 4] = uk;
            float4 vv = *(const float4*)&vtbase[(size_t)row * Sv + c * 4];
            uint4 uv;
            uv.x = f2tf(vv.x); uv.y = f2tf(vv.y); uv.z = f2tf(vv.z); uv.w = f2tf(vv.w);
            *(uint4*)&Vd[row * PADQ + c * 4] = uv;
        }
    }
    __syncthreads();

    float oacc[8][4] = {};
    float m_run[2] = { -INFINITY, -INFINITY };
    float l_run[2] = { 0.f, 0.f };

    int it = 0;
    for (int t0 = 0; t0 < Sv; t0 += 64, it ^= 1) {
        if (wid >= 8) {
            // Loaders: next tile -> alternate buffer
            if (t0 + 64 < Sv) {
                const int ltid = tid - 256;
                float* Kd = sm + 8704  + (it ^ 1) * 4352;
                float* Vd = sm + 17408 + (it ^ 1) * 4352;
                #pragma unroll
                for (int l = 0; l < 8; l++) {
                    int fid = ltid + l * 128;
                    int row = fid >> 4, c = fid & 15;
                    float4 kv = *(const float4*)&kbase[(size_t)(t0 + 64 + row) * DHv + c * 4];
                    uint4 uk;
                    uk.x = f2tf(kv.x); uk.y = f2tf(kv.y); uk.z = f2tf(kv.z); uk.w = f2tf(kv.w);
                    *(uint4*)&Kd[row * PADQ + c * 4] = uk;
                    float4 vv = *(const float4*)&vtbase[(size_t)row * Sv + t0 + 64 + c * 4];
                    uint4 uv;
                    uv.x = f2tf(vv.x); uv.y = f2tf(vv.y); uv.z = f2tf(vv.z); uv.w = f2tf(vv.w);
                    *(uint4*)&Vd[row * PADQ + c * 4] = uv;
                }
            }
        } else {
            const float* Ks = sm + 8704  + it * 4352;
            const float* Vt = sm + 17408 + it * 4352;

            // S = Q @ K^T : warp-tile m16 x n64
            float sacc[8][4] = {};
            #pragma unroll
            for (int ks = 0; ks < 64; ks += 8) {
                uint32_t a[4];
                a[0] = __float_as_uint(Qs[(wm + g) * PADQ + ks + t]);
                a[1] = __float_as_uint(Qs[(wm + g + 8) * PADQ + ks + t]);
                a[2] = __float_as_uint(Qs[(wm + g) * PADQ + ks + t + 4]);
                a[3] = __float_as_uint(Qs[(wm + g + 8) * PADQ + ks + t + 4]);
                #pragma unroll
                for (int ni = 0; ni < 8; ni++) {
                    uint32_t b[2];
                    b[0] = __float_as_uint(Ks[(ni * 8 + g) * PADQ + ks + t]);
                    b[1] = __float_as_uint(Ks[(ni * 8 + g) * PADQ + ks + t + 4]);
                    mma_tf32(sacc[ni], a, b);
                }
            }

            // Register online softmax; P -> Ps as tf32
            float corr[2];
            #pragma unroll
            for (int half = 0; half < 2; half++) {
                const int r = wm + g + half * 8;
                float mloc = -INFINITY;
                #pragma unroll
                for (int ni = 0; ni < 8; ni++)
                    mloc = fmaxf(mloc, fmaxf(sacc[ni][2*half], sacc[ni][2*half+1]));
                mloc = fmaxf(mloc, __shfl_xor_sync(0xffffffffu, mloc, 1, 4));
                mloc = fmaxf(mloc, __shfl_xor_sync(0xffffffffu, mloc, 2, 4));
                float mnew = fmaxf(m_run[half], mloc);
                corr[half] = __expf(m_run[half] - mnew);
                float sum = 0.f;
                #pragma unroll
                for (int ni = 0; ni < 8; ni++) {
                    float p0 = __expf(sacc[ni][2*half]   - mnew);
                    float p1 = __expf(sacc[ni][2*half+1] - mnew);
                    uint2 up; up.x = f2tf(p0); up.y = f2tf(p1);
                    *(uint2*)&Ps[r * PADQ + ni * 8 + 2 * t] = up;
                    sum += p0 + p1;
                }
                sum += __shfl_xor_sync(0xffffffffu, sum, 1, 4);
                sum += __shfl_xor_sync(0xffffffffu, sum, 2, 4);
                l_run[half] = l_run[half] * corr[half] + sum;
                m_run[half] = mnew;
            }
            __syncwarp();

            // Rescale output accumulators (rows g -> corr[0], g+8 -> corr[1])
            #pragma unroll
            for (int ni = 0; ni < 8; ni++) {
                oacc[ni][0] *= corr[0]; oacc[ni][1] *= corr[0];
                oacc[ni][2] *= corr[1]; oacc[ni][3] *= corr[1];
            }

            // O += P @ V : A from Ps (rows wm..wm+15), B from Vt [dh][kv]
            #pragma unroll
            for (int ks = 0; ks < 64; ks += 8) {
                uint32_t a[4];
                a[0] = __float_as_uint(Ps[(wm + g) * PADQ + ks + t]);
                a[1] = __float_as_uint(Ps[(wm + g + 8) * PADQ + ks + t]);
                a[2] = __float_as_uint(Ps[(wm + g) * PADQ + ks + t + 4]);
                a[3] = __float_as_uint(Ps[(wm + g + 8) * PADQ + ks + t + 4]);
                #pragma unroll
                for (int ni = 0; ni < 8; ni++) {
                    uint32_t b[2];
                    b[0] = __float_as_uint(Vt[(ni * 8 + g) * PADQ + ks + t]);
                    b[1] = __float_as_uint(Vt[(ni * 8 + g) * PADQ + ks + t + 4]);
                    mma_tf32(oacc[ni], a, b);
                }
            }
        }
        __syncthreads();   // buffer swap: compute done reading 'it', loaders done writing 'it^1'
    }

    // Epilogue (compute warps): normalize, write concat layout [b][s][h*DH+dh]
    if (wid < 8) {
        const int b_idx = bh / Hv;
        const int h     = bh % Hv;
        float inv0 = 1.f / l_run[0];
        float inv1 = 1.f / l_run[1];
        #pragma unroll
        for (int half = 0; half < 2; half++) {
            int r = s0 + wm + g + half * 8;
            float inv = half ? inv1 : inv0;
            float* dst = g_o + ((size_t)b_idx * Sv + r) * Dv + h * DHv;
            #pragma unroll
            for (int ni = 0; ni < 8; ni++) {
                float2 w;
                w.x = oacc[ni][2*half + 0] * inv;
                w.y = oacc[ni][2*half + 1] * inv;
                *(float2*)(dst + ni * 8 + 2 * t) = w;
            }
        }
    }
}

// ---------------------------------------------------------------------------
extern "C" void kernel_launch(void* const* d_in, const int* in_sizes, int n_in,
                              void* d_out, int out_size)
{
    const float* x  = (const float*)d_in[0];
    const float* Wq = (const float*)d_in[1];
    const float* bq = (const float*)d_in[2];
    const float* Wk = (const float*)d_in[3];
    const float* bk = (const float*)d_in[4];
    const float* Wv = (const float*)d_in[5];
    const float* bv = (const float*)d_in[6];
    const float* Wo = (const float*)d_in[7];
    const float* bo = (const float*)d_in[8];
    float* out = (float*)d_out;

    // Pre-transpose weights into [n][k] layout for mma B operands
    transpose_kernel<<<dim3(Dv/32, DHv/32, Hv), dim3(32, 8)>>>(Wq, Dv, DHv, 0);
    transpose_kernel<<<dim3(Dv/32, DHv/32, Hv), dim3(32, 8)>>>(Wk, Dv, DHv, 1);
    transpose_kernel<<<dim3(Dv/32, DHv/32, Hv), dim3(32, 8)>>>(Wv, Dv, DHv, 2);
    transpose_kernel<<<dim3(Dv/32, Dv/32, 1),   dim3(32, 8)>>>(Wo, Dv, Dv, 3);

    qkv_mma_kernel<<<dim3(Mv/128, Hv, 3), 256>>>(x, bq, bk, bv);

    size_t smem = (size_t)34816 * sizeof(float);   // 139,264 B
    cudaFuncSetAttribute(attn_kernel,
                         cudaFuncAttributeMaxDynamicSharedMemorySize, (int)smem);
    attn_kernel<<<dim3(Bv*Hv, Sv/128), 384, smem>>>();

    proj_mma_kernel<<<dim3(Mv/128, Dv/64), 256>>>(bo, out);
}

// round 17
// speedup vs baseline: 1.0390x; 1.0390x over previous
#include <cuda_runtime.h>
#include <cuda_bf16.h>
#include <cstdint>
#include <math.h>

#define Bv 2
#define Sv 2048
#define Dv 1024
#define Hv 16
#define DHv 64
#define Mv (Bv*Sv)        // 4096
#define PADK 36
#define PADQ 68

// Scratch (module-static device globals; no runtime allocation)
__device__ float g_q[(size_t)Bv*Hv*Sv*DHv];   // [b][h][s][dh]
__device__ float g_k[(size_t)Bv*Hv*Sv*DHv];   // [b][h][s][dh]
__device__ float g_vt[(size_t)Bv*Hv*DHv*Sv];  // [b][h][dh][s]  (V transposed)
__device__ float g_o[(size_t)Bv*Sv*Dv];       // [b][s][h*DH+dh]
__device__ float g_wt[(size_t)3*Hv*DHv*Dv];   // W^T per matrix/head: [mtx][h][n][k]
__device__ float g_wot[(size_t)Dv*Dv];        // Wo^T: [n][k]

// ---------------------------------------------------------------------------
// tf32 helpers (mma.sync path — tcgen05 unavailable on this build target)
// ---------------------------------------------------------------------------
__device__ __forceinline__ uint32_t f2tf(float x) {
    uint32_t r;
    asm("cvt.rna.tf32.f32 %0, %1;" : "=r"(r) : "f"(x));
    return r;
}

__device__ __forceinline__ void mma_tf32(float* c, const uint32_t* a, const uint32_t* b) {
    asm volatile(
        "mma.sync.aligned.m16n8k8.row.col.f32.tf32.tf32.f32 "
        "{%0,%1,%2,%3}, {%4,%5,%6,%7}, {%8,%9}, {%0,%1,%2,%3};"
        : "+f"(c[0]), "+f"(c[1]), "+f"(c[2]), "+f"(c[3])
        : "r"(a[0]), "r"(a[1]), "r"(a[2]), "r"(a[3]), "r"(b[0]), "r"(b[1]));
}

// ---------------------------------------------------------------------------
// Weight transpose: dst[b][c][r] = src[b][r][c].
// ---------------------------------------------------------------------------
__global__ __launch_bounds__(256) void transpose_kernel(
    const float* __restrict__ src, int R, int C, int which)
{
    __shared__ float t[32][33];
    float* dstbase = (which < 3) ? (g_wt + (size_t)which * Hv * DHv * Dv) : g_wot;

    const int b  = blockIdx.z;
    const float* s = src + (size_t)b * R * C;
    float* d       = dstbase + (size_t)b * R * C;
    const int r0 = blockIdx.x * 32, c0 = blockIdx.y * 32;
    const int tx = threadIdx.x, ty = threadIdx.y;

    #pragma unroll
    for (int i = 0; i < 4; i++)
        t[ty + 8*i][tx] = s[(size_t)(r0 + ty + 8*i) * C + c0 + tx];
    __syncthreads();
    #pragma unroll
    for (int i = 0; i < 4; i++)
        d[(size_t)(c0 + ty + 8*i) * R + r0 + tx] = t[tx][ty + 8*i];
}

// ---------------------------------------------------------------------------
// Pipelined mma.sync tf32 GEMM core: acc[128x64] += A[128xDv] @ B[64xDv]^T.
// 256 threads = 8 warps in 4(M) x 2(N); warp tile 32x32 = 2x4 m16n8k8 frags.
// Double-buffered smem + register prefetch: chunk kc+1 is fetched from gmem
// into registers during compute of chunk kc, then converted+stored to the
// alternate buffer.  ONE barrier per 32-k chunk (was 2).
// Dynamic smem layout (floats): As0@0[4608] As1@4608 | Bs0@9216[2304] Bs1@11520
// total 13824 floats = 55296 B.
// ---------------------------------------------------------------------------
#define GEMM_SMEM_FLOATS 13824

__device__ __forceinline__ void gemm_mma_128x64_pipe(
    const float* __restrict__ Arows, const float* __restrict__ Brows,
    float acc[2][4][4], float* sm)
{
    const int tid  = threadIdx.x;
    const int wid  = tid >> 5;
    const int lane = tid & 31;
    const int g    = lane >> 2;
    const int t    = lane & 3;
    const int wm   = (wid & 3) * 32;
    const int wn   = (wid >> 2) * 32;

    float4 ra[4], rb[2];

    // Prefetch + store chunk 0 into buffer 0
    #pragma unroll
    for (int l = 0; l < 4; l++) {
        int fid = tid + l * 256;
        ra[l] = *(const float4*)&Arows[(size_t)(fid >> 3) * Dv + (fid & 7) * 4];
    }
    #pragma unroll
    for (int l = 0; l < 2; l++) {
        int fid = tid + l * 256;
        rb[l] = *(const float4*)&Brows[(size_t)(fid >> 3) * Dv + (fid & 7) * 4];
    }
    {
        float* As = sm;
        float* Bs = sm + 9216;
        #pragma unroll
        for (int l = 0; l < 4; l++) {
            int fid = tid + l * 256;
            uint4 u;
            u.x = f2tf(ra[l].x); u.y = f2tf(ra[l].y);
            u.z = f2tf(ra[l].z); u.w = f2tf(ra[l].w);
            *(uint4*)&As[(fid >> 3) * PADK + (fid & 7) * 4] = u;
        }
        #pragma unroll
        for (int l = 0; l < 2; l++) {
            int fid = tid + l * 256;
            uint4 u;
            u.x = f2tf(rb[l].x); u.y = f2tf(rb[l].y);
            u.z = f2tf(rb[l].z); u.w = f2tf(rb[l].w);
            *(uint4*)&Bs[(fid >> 3) * PADK + (fid & 7) * 4] = u;
        }
    }
    __syncthreads();

    int p = 0;
    for (int kc = 0; kc < Dv / 32; kc++) {
        const bool has_next = (kc + 1) < (Dv / 32);

        // Prefetch chunk kc+1 into registers (latency hidden by compute)
        if (has_next) {
            #pragma unroll
            for (int l = 0; l < 4; l++) {
                int fid = tid + l * 256;
                ra[l] = *(const float4*)&Arows[(size_t)(fid >> 3) * Dv + (kc + 1) * 32 + (fid & 7) * 4];
            }
            #pragma unroll
            for (int l = 0; l < 2; l++) {
                int fid = tid + l * 256;
                rb[l] = *(const float4*)&Brows[(size_t)(fid >> 3) * Dv + (kc + 1) * 32 + (fid & 7) * 4];
            }
        }

        const float* As = sm + p * 4608;
        const float* Bs = sm + 9216 + p * 2304;

        #pragma unroll
        for (int ks = 0; ks < 32; ks += 8) {
            uint32_t a[2][4], b[4][2];
            #pragma unroll
            for (int mi = 0; mi < 2; mi++) {
                int r0 = wm + mi * 16 + g;
                a[mi][0] = __float_as_uint(As[r0 * PADK + ks + t]);
                a[mi][1] = __float_as_uint(As[(r0 + 8) * PADK + ks + t]);
                a[mi][2] = __float_as_uint(As[r0 * PADK + ks + t + 4]);
                a[mi][3] = __float_as_uint(As[(r0 + 8) * PADK + ks + t + 4]);
            }
            #pragma unroll
            for (int ni = 0; ni < 4; ni++) {
                int nr = wn + ni * 8 + g;
                b[ni][0] = __float_as_uint(Bs[nr * PADK + ks + t]);
                b[ni][1] = __float_as_uint(Bs[nr * PADK + ks + t + 4]);
            }
            #pragma unroll
            for (int mi = 0; mi < 2; mi++)
                #pragma unroll
                for (int ni = 0; ni < 4; ni++)
                    mma_tf32(acc[mi][ni], a[mi], b[ni]);
        }

        // Drain prefetch into the alternate buffer (disjoint from buf p)
        if (has_next) {
            float* Ad = sm + (p ^ 1) * 4608;
            float* Bd = sm + 9216 + (p ^ 1) * 2304;
            #pragma unroll
            for (int l = 0; l < 4; l++) {
                int fid = tid + l * 256;
                uint4 u;
                u.x = f2tf(ra[l].x); u.y = f2tf(ra[l].y);
                u.z = f2tf(ra[l].z); u.w = f2tf(ra[l].w);
                *(uint4*)&Ad[(fid >> 3) * PADK + (fid & 7) * 4] = u;
            }
            #pragma unroll
            for (int l = 0; l < 2; l++) {
                int fid = tid + l * 256;
                uint4 u;
                u.x = f2tf(rb[l].x); u.y = f2tf(rb[l].y);
                u.z = f2tf(rb[l].z); u.w = f2tf(rb[l].w);
                *(uint4*)&Bd[(fid >> 3) * PADK + (fid & 7) * 4] = u;
            }
        }
        __syncthreads();   // reads of buf p complete; buf p^1 ready
        p ^= 1;
    }
}

// ---------------------------------------------------------------------------
// Kernel 1: QKV projection via pipelined mma.sync tf32.
// grid(Mv/128, H, 3), block 256.  V (mtx==2) written TRANSPOSED to g_vt.
// ---------------------------------------------------------------------------
__global__ __launch_bounds__(256) void qkv_mma_kernel(
    const float* __restrict__ x,
    const float* __restrict__ bq,
    const float* __restrict__ bk,
    const float* __restrict__ bv)
{
    extern __shared__ float smdyn[];

    const int h   = blockIdx.y;
    const int mtx = blockIdx.z;
    const int r0  = blockIdx.x * 128;

    const float* Brows = g_wt + ((size_t)(mtx * Hv + h) * DHv) * Dv;
    const float* bias  = ((mtx == 0) ? bq : (mtx == 1) ? bk : bv) + h * DHv;

    float acc[2][4][4] = {};
    gemm_mma_128x64_pipe(x + (size_t)r0 * Dv, Brows, acc, smdyn);

    const int lane = threadIdx.x & 31;
    const int wid  = threadIdx.x >> 5;
    const int g    = lane >> 2;
    const int t    = lane & 3;
    const int wm   = (wid & 3) * 32;
    const int wn   = (wid >> 2) * 32;

    if (mtx == 2) {
        // transposed store: g_vt[(b*Hv+h)*DHv + col][s]
        #pragma unroll
        for (int mi = 0; mi < 2; mi++) {
            #pragma unroll
            for (int ni = 0; ni < 4; ni++) {
                int col = wn + ni * 8 + 2 * t;
                #pragma unroll
                for (int half = 0; half < 2; half++) {
                    int m = r0 + wm + mi * 16 + g + half * 8;
                    int b = m >> 11;
                    int s = m & (Sv - 1);
                    float* base = g_vt + ((size_t)(b * Hv + h) * DHv) * Sv;
                    base[(size_t)(col + 0) * Sv + s] = acc[mi][ni][2*half + 0] + bias[col + 0];
                    base[(size_t)(col + 1) * Sv + s] = acc[mi][ni][2*half + 1] + bias[col + 1];
                }
            }
        }
    } else {
        float* out = (mtx == 0) ? g_q : g_k;
        #pragma unroll
        for (int mi = 0; mi < 2; mi++) {
            #pragma unroll
            for (int ni = 0; ni < 4; ni++) {
                int col = wn + ni * 8 + 2 * t;
                #pragma unroll
                for (int half = 0; half < 2; half++) {
                    int m = r0 + wm + mi * 16 + g + half * 8;
                    int b = m >> 11;
                    int s = m & (Sv - 1);
                    float* dst = out + ((size_t)(b * Hv + h) * Sv + s) * DHv + col;
                    float2 w;
                    w.x = acc[mi][ni][2*half + 0] + bias[col + 0];
                    w.y = acc[mi][ni][2*half + 1] + bias[col + 1];
                    *(float2*)dst = w;
                }
            }
        }
    }
}

// ---------------------------------------------------------------------------
// Kernel 3: output projection via pipelined mma.sync tf32.
// grid(Mv/128, Dv/64), block 256.
// ---------------------------------------------------------------------------
__global__ __launch_bounds__(256) void proj_mma_kernel(
    const float* __restrict__ bo, float* __restrict__ out)
{
    extern __shared__ float smdyn[];

    const int r0 = blockIdx.x * 128;
    const int n0 = blockIdx.y * 64;

    float acc[2][4][4] = {};
    gemm_mma_128x64_pipe(g_o + (size_t)r0 * Dv, g_wot + (size_t)n0 * Dv, acc, smdyn);

    const int lane = threadIdx.x & 31;
    const int wid  = threadIdx.x >> 5;
    const int g    = lane >> 2;
    const int t    = lane & 3;
    const int wm   = (wid & 3) * 32;
    const int wn   = (wid >> 2) * 32;

    #pragma unroll
    for (int mi = 0; mi < 2; mi++) {
        #pragma unroll
        for (int ni = 0; ni < 4; ni++) {
            int col = n0 + wn + ni * 8 + 2 * t;
            #pragma unroll
            for (int half = 0; half < 2; half++) {
                int m = r0 + wm + mi * 16 + g + half * 8;
                float* dst = out + (size_t)m * Dv + col;
                float2 w;
                w.x = acc[mi][ni][2*half + 0] + bo[col + 0];
                w.y = acc[mi][ni][2*half + 1] + bo[col + 1];
                *(float2*)dst = w;
            }
        }
    }
}

// ---------------------------------------------------------------------------
// Kernel 2: flash attention (exact R13 config — validated 629us).
// grid(B*H, S/64), block 256.  Warps 0-3 compute, warps 4-7 loaders.
// Smem (floats): Qs@0[64*68] | Ks0@4352 Ks1@8704 | Vt0@13056 Vt1@17408 |
//                Ps@21760[64*68]   total 26112 f = 104448 B (2 CTA/SM)
// ---------------------------------------------------------------------------
__global__ __launch_bounds__(256) void attn_kernel()
{
    extern __shared__ float sm[];
    float* Qs = sm;
    float* Ps = sm + 21760;

    const int bh  = blockIdx.x;                 // b*H + h
    const int s0  = blockIdx.y * 64;
    const int tid = threadIdx.x;
    const int wid = tid >> 5;
    const int lane = tid & 31;
    const int g   = lane >> 2;
    const int t   = lane & 3;
    const int wm  = (wid & 3) * 16;

    const float* qbase  = g_q  + (size_t)bh * Sv * DHv;
    const float* kbase  = g_k  + (size_t)bh * Sv * DHv;
    const float* vtbase = g_vt + (size_t)bh * DHv * Sv;

    // All threads: Q tile -> tf32, pre-scaled by 1/8 (exact)
    #pragma unroll
    for (int l = 0; l < 4; l++) {
        int fid = tid + l * 256;
        int row = fid >> 4, c = fid & 15;
        float4 v = *(const float4*)&qbase[(size_t)(s0 + row) * DHv + c * 4];
        uint4 u;
        u.x = f2tf(v.x * 0.125f); u.y = f2tf(v.y * 0.125f);
        u.z = f2tf(v.z * 0.125f); u.w = f2tf(v.w * 0.125f);
        *(uint4*)&Qs[row * PADQ + c * 4] = u;
    }

    // Loaders fill buffer 0 with tile 0
    if (wid >= 4) {
        const int ltid = tid - 128;
        float* Kd = sm + 4352;
        float* Vd = sm + 13056;
        #pragma unroll
        for (int l = 0; l < 8; l++) {
            int fid = ltid + l * 128;
            int row = fid >> 4, c = fid & 15;
            float4 kv = *(const float4*)&kbase[(size_t)row * DHv + c * 4];
            uint4 uk;
            uk.x = f2tf(kv.x); uk.y = f2tf(kv.y); uk.z = f2tf(kv.z); uk.w = f2tf(kv.w);
            *(uint4*)&Kd[row * PADQ + c * 4] = uk;
            float4 vv = *(const float4*)&vtbase[(size_t)row * Sv + c * 4];
            uint4 uv;
            uv.x = f2tf(vv.x); uv.y = f2tf(vv.y); uv.z = f2tf(vv.z); uv.w = f2tf(vv.w);
            *(uint4*)&Vd[row * PADQ + c * 4] = uv;
        }
    }
    __syncthreads();

    float oacc[8][4] = {};
    float m_run[2] = { -INFINITY, -INFINITY };
    float l_run[2] = { 0.f, 0.f };

    int it = 0;
    for (int t0 = 0; t0 < Sv; t0 += 64, it ^= 1) {
        if (wid >= 4) {
            // Loaders: next tile -> alternate buffer
            if (t0 + 64 < Sv) {
                const int ltid = tid - 128;
                float* Kd = sm + 4352  + (it ^ 1) * 4352;
                float* Vd = sm + 13056 + (it ^ 1) * 4352;
                #pragma unroll
                for (int l = 0; l < 8; l++) {
                    int fid = ltid + l * 128;
                    int row = fid >> 4, c = fid & 15;
                    float4 kv = *(const float4*)&kbase[(size_t)(t0 + 64 + row) * DHv + c * 4];
                    uint4 uk;
                    uk.x = f2tf(kv.x); uk.y = f2tf(kv.y); uk.z = f2tf(kv.z); uk.w = f2tf(kv.w);
                    *(uint4*)&Kd[row * PADQ + c * 4] = uk;
                    float4 vv = *(const float4*)&vtbase[(size_t)row * Sv + t0 + 64 + c * 4];
                    uint4 uv;
                    uv.x = f2tf(vv.x); uv.y = f2tf(vv.y); uv.z = f2tf(vv.z); uv.w = f2tf(vv.w);
                    *(uint4*)&Vd[row * PADQ + c * 4] = uv;
                }
            }
        } else {
            const float* Ks = sm + 4352  + it * 4352;
            const float* Vt = sm + 13056 + it * 4352;

            // S = Q @ K^T : warp-tile m16 x n64
            float sacc[8][4] = {};
            #pragma unroll
            for (int ks = 0; ks < 64; ks += 8) {
                uint32_t a[4];
                a[0] = __float_as_uint(Qs[(wm + g) * PADQ + ks + t]);
                a[1] = __float_as_uint(Qs[(wm + g + 8) * PADQ + ks + t]);
                a[2] = __float_as_uint(Qs[(wm + g) * PADQ + ks + t + 4]);
                a[3] = __float_as_uint(Qs[(wm + g + 8) * PADQ + ks + t + 4]);
                #pragma unroll
                for (int ni = 0; ni < 8; ni++) {
                    uint32_t b[2];
                    b[0] = __float_as_uint(Ks[(ni * 8 + g) * PADQ + ks + t]);
                    b[1] = __float_as_uint(Ks[(ni * 8 + g) * PADQ + ks + t + 4]);
                    mma_tf32(sacc[ni], a, b);
                }
            }

            // Register online softmax; P -> Ps as tf32
            float corr[2];
            #pragma unroll
            for (int half = 0; half < 2; half++) {
                const int r = wm + g + half * 8;
                float mloc = -INFINITY;
                #pragma unroll
                for (int ni = 0; ni < 8; ni++)
                    mloc = fmaxf(mloc, fmaxf(sacc[ni][2*half], sacc[ni][2*half+1]));
                mloc = fmaxf(mloc, __shfl_xor_sync(0xffffffffu, mloc, 1, 4));
                mloc = fmaxf(mloc, __shfl_xor_sync(0xffffffffu, mloc, 2, 4));
                float mnew = fmaxf(m_run[half], mloc);
                corr[half] = __expf(m_run[half] - mnew);
                float sum = 0.f;
                #pragma unroll
                for (int ni = 0; ni < 8; ni++) {
                    float p0 = __expf(sacc[ni][2*half]   - mnew);
                    float p1 = __expf(sacc[ni][2*half+1] - mnew);
                    uint2 up; up.x = f2tf(p0); up.y = f2tf(p1);
                    *(uint2*)&Ps[r * PADQ + ni * 8 + 2 * t] = up;
                    sum += p0 + p1;
                }
                sum += __shfl_xor_sync(0xffffffffu, sum, 1, 4);
                sum += __shfl_xor_sync(0xffffffffu, sum, 2, 4);
                l_run[half] = l_run[half] * corr[half] + sum;
                m_run[half] = mnew;
            }
            __syncwarp();

            // Rescale output accumulators (rows g -> corr[0], g+8 -> corr[1])
            #pragma unroll
            for (int ni = 0; ni < 8; ni++) {
                oacc[ni][0] *= corr[0]; oacc[ni][1] *= corr[0];
                oacc[ni][2] *= corr[1]; oacc[ni][3] *= corr[1];
            }

            // O += P @ V : A from Ps (rows wm..wm+15), B from Vt [dh][kv]
            #pragma unroll
            for (int ks = 0; ks < 64; ks += 8) {
                uint32_t a[4];
                a[0] = __float_as_uint(Ps[(wm + g) * PADQ + ks + t]);
                a[1] = __float_as_uint(Ps[(wm + g + 8) * PADQ + ks + t]);
                a[2] = __float_as_uint(Ps[(wm + g) * PADQ + ks + t + 4]);
                a[3] = __float_as_uint(Ps[(wm + g + 8) * PADQ + ks + t + 4]);
                #pragma unroll
                for (int ni = 0; ni < 8; ni++) {
                    uint32_t b[2];
                    b[0] = __float_as_uint(Vt[(ni * 8 + g) * PADQ + ks + t]);
                    b[1] = __float_as_uint(Vt[(ni * 8 + g) * PADQ + ks + t + 4]);
                    mma_tf32(oacc[ni], a, b);
                }
            }
        }
        __syncthreads();   // buffer swap: compute done reading 'it', loaders done writing 'it^1'
    }

    // Epilogue (compute warps): normalize, write concat layout [b][s][h*DH+dh]
    if (wid < 4) {
        const int b_idx = bh / Hv;
        const int h     = bh % Hv;
        float inv0 = 1.f / l_run[0];
        float inv1 = 1.f / l_run[1];
        #pragma unroll
        for (int half = 0; half < 2; half++) {
            int r = s0 + wm + g + half * 8;
            float inv = half ? inv1 : inv0;
            float* dst = g_o + ((size_t)b_idx * Sv + r) * Dv + h * DHv;
            #pragma unroll
            for (int ni = 0; ni < 8; ni++) {
                float2 w;
                w.x = oacc[ni][2*half + 0] * inv;
                w.y = oacc[ni][2*half + 1] * inv;
                *(float2*)(dst + ni * 8 + 2 * t) = w;
            }
        }
    }
}

// ---------------------------------------------------------------------------
extern "C" void kernel_launch(void* const* d_in, const int* in_sizes, int n_in,
                              void* d_out, int out_size)
{
    const float* x  = (const float*)d_in[0];
    const float* Wq = (const float*)d_in[1];
    const float* bq = (const float*)d_in[2];
    const float* Wk = (const float*)d_in[3];
    const float* bk = (const float*)d_in[4];
    const float* Wv = (const float*)d_in[5];
    const float* bv = (const float*)d_in[6];
    const float* Wo = (const float*)d_in[7];
    const float* bo = (const float*)d_in[8];
    float* out = (float*)d_out;

    // Pre-transpose weights into [n][k] layout for mma B operands
    transpose_kernel<<<dim3(Dv/32, DHv/32, Hv), dim3(32, 8)>>>(Wq, Dv, DHv, 0);
    transpose_kernel<<<dim3(Dv/32, DHv/32, Hv), dim3(32, 8)>>>(Wk, Dv, DHv, 1);
    transpose_kernel<<<dim3(Dv/32, DHv/32, Hv), dim3(32, 8)>>>(Wv, Dv, DHv, 2);
    transpose_kernel<<<dim3(Dv/32, Dv/32, 1),   dim3(32, 8)>>>(Wo, Dv, Dv, 3);

    size_t gsm = (size_t)GEMM_SMEM_FLOATS * sizeof(float);   // 55,296 B
    cudaFuncSetAttribute(qkv_mma_kernel,
                         cudaFuncAttributeMaxDynamicSharedMemorySize, (int)gsm);
    cudaFuncSetAttribute(proj_mma_kernel,
                         cudaFuncAttributeMaxDynamicSharedMemorySize, (int)gsm);

    qkv_mma_kernel<<<dim3(Mv/128, Hv, 3), 256, gsm>>>(x, bq, bk, bv);

    size_t smem = (size_t)26112 * sizeof(float);   // 104,448 B
    cudaFuncSetAttribute(attn_kernel,
                         cudaFuncAttributeMaxDynamicSharedMemorySize, (int)smem);
    attn_kernel<<<dim3(Bv*Hv, Sv/64), 256, smem>>>();

    proj_mma_kernel<<<dim3(Mv/128, Dv/64), 256, gsm>>>(bo, out);
}